// round 9
// baseline (speedup 1.0000x reference)
#include <cuda_runtime.h>
#include <cstdint>
#include <cstddef>

// ============================================================================
// y = (x_q @ W) * (x_scale * 0.0123) + bias     [M,K]x[K,N] = 2048x4096x11008
// sm_100 base target. cp.async + ldmatrix + mma.sync.m16n8k32.s8.s8.s32.
// R9 == R8 resubmit (R8 never executed: container infra flake, same signature
// as R0's no-op stub and R6; R7 passed on identical resubmission).
// R8: GEMM K-loop restructured into 2-kt blocks with 6 stages:
//     one wait_group/commit/__syncthreads per TWO k-tiles (32 barriers, was 64)
//     -> longer uninterrupted mma runs, tensor idle down. 96KB smem, 2 CTAs/SM.
// ============================================================================

#define MDIM 2048
#define KDIM 4096
#define NDIM 11008

#define BM 128
#define BN 128
#define BK 64
#define STAGES 6
#define NIT (KDIM / BK)   /* 64 */
#define NBLK (NIT / 2)    /* 32 two-kt blocks */
#define NTHREADS 128

#define A_TILE (BM * BK)          /* 8192 B */
#define B_TILE (BN * BK)          /* 8192 B */
#define STAGE_BYTES (A_TILE + B_TILE)
#define SMEM_TOTAL (STAGES * STAGE_BYTES) /* 98304 */

// ---------------- device scratch (__device__ globals: allowed) --------------
__device__ __align__(128) int8_t g_xq[(size_t)MDIM * KDIM];  // [M][K]
__device__ __align__(128) int8_t g_wt[(size_t)NDIM * KDIM];  // [N][K] (= W^T)
__device__ int g_absmax_bits;  // static zero; idempotent across graph replays

// smem tile layout: 16B chunk c of row r at r*64 + (c ^ ((r>>1)&3))*16.
__device__ __forceinline__ uint32_t tile_off(uint32_t r, uint32_t c) {
    return r * 64u + ((c ^ ((r >> 1) & 3u)) << 4);
}

__device__ __forceinline__ uint32_t smem_u32(const void* p) {
    uint32_t a;
    asm("{ .reg .u64 t; cvta.to.shared.u64 t, %1; cvt.u32.u64 %0, t; }" : "=r"(a) : "l"(p));
    return a;
}
#define CP_ASYNC16(smem, gptr) \
    asm volatile("cp.async.cg.shared.global [%0], [%1], 16;" ::"r"(smem), "l"(gptr) : "memory")
#define CP_COMMIT() asm volatile("cp.async.commit_group;" ::: "memory")
#define CP_WAIT1() asm volatile("cp.async.wait_group 1;" ::: "memory")

__device__ __forceinline__ void ldsm_x4(uint32_t* r, uint32_t addr) {
    asm volatile("ldmatrix.sync.aligned.m8n8.x4.shared.b16 {%0,%1,%2,%3}, [%4];"
                 : "=r"(r[0]), "=r"(r[1]), "=r"(r[2]), "=r"(r[3]) : "r"(addr));
}
__device__ __forceinline__ void mma_s8(int* d, const uint32_t* a, const uint32_t* b) {
    asm volatile(
        "mma.sync.aligned.m16n8k32.row.col.s32.s8.s8.s32 "
        "{%0,%1,%2,%3}, {%4,%5,%6,%7}, {%8,%9}, {%0,%1,%2,%3};"
        : "+r"(d[0]), "+r"(d[1]), "+r"(d[2]), "+r"(d[3])
        : "r"(a[0]), "r"(a[1]), "r"(a[2]), "r"(a[3]), "r"(b[0]), "r"(b[1]));
}

// ============================ kernel 1: absmax ==============================
__global__ void k_absmax(const float4* __restrict__ x, int n4) {
    float m = 0.0f;
    for (int i = blockIdx.x * blockDim.x + threadIdx.x; i < n4; i += gridDim.x * blockDim.x) {
        float4 v = x[i];
        m = fmaxf(m, fmaxf(fmaxf(fabsf(v.x), fabsf(v.y)), fmaxf(fabsf(v.z), fabsf(v.w))));
    }
    #pragma unroll
    for (int o = 16; o; o >>= 1) m = fmaxf(m, __shfl_xor_sync(0xFFFFFFFFu, m, o));
    __shared__ float sm[8];
    if ((threadIdx.x & 31) == 0) sm[threadIdx.x >> 5] = m;
    __syncthreads();
    if (threadIdx.x < 32) {
        float v = (threadIdx.x < 8) ? sm[threadIdx.x] : 0.0f;
        #pragma unroll
        for (int o = 4; o; o >>= 1) v = fmaxf(v, __shfl_xor_sync(0xFFFFFFFFu, v, o));
        if (threadIdx.x == 0) atomicMax(&g_absmax_bits, __float_as_int(v));  // v >= 0
    }
}

// ================== kernel 2: quantize x -> int8 [M][K] =====================
__device__ __forceinline__ int quant1(float v, float s) {
    float q = rintf(__fdiv_rn(v, s));  // IEEE div + round-half-even == jnp
    return (int)fminf(fmaxf(q, -128.0f), 127.0f);
}
__global__ void k_quant(const float4* __restrict__ x, int n4) {
    int i = blockIdx.x * blockDim.x + threadIdx.x;
    if (i >= n4) return;
    float s = __int_as_float(g_absmax_bits) * (1.0f / 128.0f);  // exact /128
    float4 v = x[i];
    uint32_t b0 = (uint32_t)(quant1(v.x, s) & 0xFF);
    uint32_t b1 = (uint32_t)(quant1(v.y, s) & 0xFF);
    uint32_t b2 = (uint32_t)(quant1(v.z, s) & 0xFF);
    uint32_t b3 = (uint32_t)(quant1(v.w, s) & 0xFF);
    reinterpret_cast<uint32_t*>(g_xq)[i] = b0 | (b1 << 8) | (b2 << 16) | (b3 << 24);
}

// ======== kernel 3: W [K][N] -> g_wt [N][K], register 4x4 PRMT transpose ====
__global__ void k_trans(const int8_t* __restrict__ W) {
    __shared__ uint32_t ts[64][17];
    int t = threadIdx.x;  // 256 threads
    int v0 = reinterpret_cast<const int*>(W)[t];
    int w_is32 = (__syncthreads_count(v0 >= -128 && v0 < 128) >= 250) ? 1 : 0;

    int n0 = blockIdx.x * 64, k0 = blockIdx.y * 64;
    int nb = t & 15, kb = t >> 4;

    uint32_t r[4];
    if (w_is32) {
        const int* W32 = reinterpret_cast<const int*>(W);
        #pragma unroll
        for (int i = 0; i < 4; ++i) {
            int4 v = *reinterpret_cast<const int4*>(
                &W32[(size_t)(k0 + kb * 4 + i) * NDIM + n0 + nb * 4]);
            r[i] = (v.x & 255) | ((v.y & 255) << 8) | ((v.z & 255) << 16)
                 | ((uint32_t)v.w << 24);
        }
    } else {
        #pragma unroll
        for (int i = 0; i < 4; ++i)
            r[i] = *reinterpret_cast<const uint32_t*>(
                &W[(size_t)(k0 + kb * 4 + i) * NDIM + n0 + nb * 4]);
    }
    uint32_t lo01 = __byte_perm(r[0], r[1], 0x5140);
    uint32_t hi01 = __byte_perm(r[0], r[1], 0x7362);
    uint32_t lo23 = __byte_perm(r[2], r[3], 0x5140);
    uint32_t hi23 = __byte_perm(r[2], r[3], 0x7362);
    ts[nb * 4 + 0][kb] = __byte_perm(lo01, lo23, 0x5410);
    ts[nb * 4 + 1][kb] = __byte_perm(lo01, lo23, 0x7632);
    ts[nb * 4 + 2][kb] = __byte_perm(hi01, hi23, 0x5410);
    ts[nb * 4 + 3][kb] = __byte_perm(hi01, hi23, 0x7632);
    __syncthreads();
    int n = t >> 2, ck = t & 3;
    uint32_t o0 = ts[n][ck * 4 + 0], o1 = ts[n][ck * 4 + 1];
    uint32_t o2 = ts[n][ck * 4 + 2], o3 = ts[n][ck * 4 + 3];
    *reinterpret_cast<uint4*>(&g_wt[(size_t)(n0 + n) * KDIM + k0 + ck * 16]) =
        make_uint4(o0, o1, o2, o3);
}

// ============================ kernel 4: GEMM ================================
// 128 threads; 4 warps in 2(M) x 2(N), warp tile 64x64; 2-kt blocks, 6 stages.
__global__ __launch_bounds__(NTHREADS, 2) void k_gemm(const float* __restrict__ bias,
                                                      float* __restrict__ out) {
    extern __shared__ char smem[];
    const uint32_t sb = smem_u32(smem);
    const int tid = threadIdx.x, lane = tid & 31;
    const int wid = tid >> 5;
    const int m0 = blockIdx.y * BM, n0 = blockIdx.x * BN;
    const int wm = (wid & 1) * 64;
    const int wn = (wid >> 1) * 64;

    const int8_t* ga = g_xq + (size_t)m0 * KDIM;
    const int8_t* gw = g_wt + (size_t)n0 * KDIM;

    auto load_stage = [&](int s, int kt) {
        uint32_t abase = sb + s * STAGE_BYTES;
        uint32_t bbase = abase + A_TILE;
        int k0 = kt * BK;
        #pragma unroll
        for (int i = 0; i < 4; ++i) {
            int idx = tid + i * NTHREADS;  // 0..511
            uint32_t r = (uint32_t)idx >> 2, c = (uint32_t)idx & 3;
            CP_ASYNC16(abase + tile_off(r, c), ga + (size_t)r * KDIM + k0 + c * 16);
            CP_ASYNC16(bbase + tile_off(r, c), gw + (size_t)r * KDIM + k0 + c * 16);
        }
    };

    int acc[4][8][4];
    #pragma unroll
    for (int a = 0; a < 4; ++a)
        #pragma unroll
        for (int b = 0; b < 8; ++b)
            #pragma unroll
            for (int c = 0; c < 4; ++c) acc[a][b][c] = 0;

    // one k32 step: fragments from stage slot, column pair j in {0,1}
    auto compute_k32 = [&](uint32_t abase, uint32_t bbase, int j) {
        uint32_t af[4][4], bf[4][4];
        #pragma unroll
        for (int f = 0; f < 4; ++f) {
            uint32_t r = (uint32_t)(wm + f * 16 + (lane & 15));
            uint32_t c = (uint32_t)(2 * j + (lane >> 4));
            ldsm_x4(af[f], abase + tile_off(r, c));
        }
        #pragma unroll
        for (int p = 0; p < 4; ++p) {
            uint32_t r = (uint32_t)(wn + p * 16 + (lane & 7) + ((lane >> 4) << 3));
            uint32_t c = (uint32_t)(2 * j + ((lane >> 3) & 1));
            ldsm_x4(bf[p], bbase + tile_off(r, c));
        }
        #pragma unroll
        for (int f = 0; f < 4; ++f)
            #pragma unroll
            for (int nf = 0; nf < 8; ++nf)
                mma_s8(acc[f][nf], af[f], &bf[nf >> 1][(nf & 1) * 2]);
    };

    // prologue: 2 groups x 2 stages (blocks 0 and 1)
    load_stage(0, 0);
    load_stage(1, 1);
    CP_COMMIT();
    load_stage(2, 2);
    load_stage(3, 3);
    CP_COMMIT();

    int slot = 0;  // slot of first stage of current block; cycles 0,2,4 mod 6
    #pragma unroll 1
    for (int t = 0; t < NBLK; ++t) {
        CP_WAIT1();      // pending <=1 group -> this block's group complete
        __syncthreads(); // orders last block's reads before this block's writes
        {
            int pf = 2 * t + 4;  // prefetch block t+2
            if (pf < NIT) {
                int ps = slot + 4; if (ps >= STAGES) ps -= STAGES;
                load_stage(ps, pf);
                int ps2 = ps + 1; if (ps2 >= STAGES) ps2 -= STAGES;
                load_stage(ps2, pf + 1);
            }
        }
        CP_COMMIT();  // always commit -> uniform group counting (tail-safe)

        // two k-tiles, four k32 steps, no barriers in between
        uint32_t a0 = sb + slot * STAGE_BYTES;
        compute_k32(a0, a0 + A_TILE, 0);
        compute_k32(a0, a0 + A_TILE, 1);
        int slot2 = slot + 1; if (slot2 >= STAGES) slot2 -= STAGES;
        uint32_t a1 = sb + slot2 * STAGE_BYTES;
        compute_k32(a1, a1 + A_TILE, 0);
        compute_k32(a1, a1 + A_TILE, 1);

        slot += 2; if (slot >= STAGES) slot -= STAGES;
    }

    // ---------------- epilogue: y = acc * sc + bias ----------------
    const float sc = (__int_as_float(g_absmax_bits) * (1.0f / 128.0f)) * 0.0123f;
    const int g = lane >> 2, t4 = lane & 3;
    #pragma unroll
    for (int f = 0; f < 4; ++f) {
        #pragma unroll
        for (int nf = 0; nf < 8; ++nf) {
            int col = n0 + wn + nf * 8 + 2 * t4;
            float b0 = bias[col], b1 = bias[col + 1];
            #pragma unroll
            for (int h = 0; h < 2; ++h) {
                int row = m0 + wm + f * 16 + g + h * 8;
                float2 v;
                v.x = fmaf((float)acc[f][nf][2 * h + 0], sc, b0);
                v.y = fmaf((float)acc[f][nf][2 * h + 1], sc, b1);
                *reinterpret_cast<float2*>(&out[(size_t)row * NDIM + col]) = v;
            }
        }
    }
}

// ============================ host launcher =================================
extern "C" void kernel_launch(void* const* d_in, const int* in_sizes, int n_in,
                              void* d_out, int out_size) {
    const float* x = nullptr;
    const int8_t* W = nullptr;
    const float* bias = nullptr;
    for (int i = 0; i < n_in; ++i) {
        long long sz = in_sizes[i];
        if (sz == (long long)MDIM * KDIM) x = (const float*)d_in[i];
        else if (sz == (long long)KDIM * NDIM) W = (const int8_t*)d_in[i];
        else if (sz == (long long)NDIM) bias = (const float*)d_in[i];
    }
    float* out = (float*)d_out;

    const int n4 = MDIM * KDIM / 4;
    k_absmax<<<1024, 256>>>((const float4*)x, n4);
    k_quant<<<n4 / 256, 256>>>((const float4*)x, n4);
    k_trans<<<dim3(NDIM / 64, KDIM / 64), 256>>>(W);

    cudaFuncSetAttribute(k_gemm, cudaFuncAttributeMaxDynamicSharedMemorySize, SMEM_TOTAL);
    k_gemm<<<dim3(NDIM / BN, MDIM / BM), NTHREADS, SMEM_TOTAL>>>(bias, out);
}

// round 10
// speedup vs baseline: 1.1423x; 1.1423x over previous
#include <cuda_runtime.h>
#include <cstdint>
#include <cstddef>

// ============================================================================
// y = (x_q @ W) * (x_scale * 0.0123) + bias     [M,K]x[K,N] = 2048x4096x11008
// sm_100 base target. cp.async + ldmatrix + mma.sync.m16n8k32.s8.s8.s32.
// R10 = R7 structure (5 stages, wait_group 3, per-kt barrier — measured best:
//       GEMM 231us / tensor 74.3%) + intra-kt fragment software pipelining:
//       ldsm(j0) -> cp.async prefetch -> ldsm(j1) -> mma(j0) -> mma(j1),
//       hiding LDSM latency under the cp.async issue burst and the j0 mma run.
// R8's 2-kt-block experiment REGRESSED (tensor 62.7%): wait_group 1 with 2-kt
// groups cut effective pipeline depth from 3 kt to 2 kt -> reverted.
// ============================================================================

#define MDIM 2048
#define KDIM 4096
#define NDIM 11008

#define BM 128
#define BN 128
#define BK 64
#define STAGES 5
#define NIT (KDIM / BK) /* 64 */
#define NTHREADS 128

#define A_TILE (BM * BK)          /* 8192 B */
#define B_TILE (BN * BK)          /* 8192 B */
#define STAGE_BYTES (A_TILE + B_TILE)
#define SMEM_TOTAL (STAGES * STAGE_BYTES) /* 81920 */

// ---------------- device scratch (__device__ globals: allowed) --------------
__device__ __align__(128) int8_t g_xq[(size_t)MDIM * KDIM];  // [M][K]
__device__ __align__(128) int8_t g_wt[(size_t)NDIM * KDIM];  // [N][K] (= W^T)
__device__ int g_absmax_bits;  // static zero; idempotent across graph replays

// smem tile layout: 16B chunk c of row r at r*64 + (c ^ ((r>>1)&3))*16.
__device__ __forceinline__ uint32_t tile_off(uint32_t r, uint32_t c) {
    return r * 64u + ((c ^ ((r >> 1) & 3u)) << 4);
}

__device__ __forceinline__ uint32_t smem_u32(const void* p) {
    uint32_t a;
    asm("{ .reg .u64 t; cvta.to.shared.u64 t, %1; cvt.u32.u64 %0, t; }" : "=r"(a) : "l"(p));
    return a;
}
#define CP_ASYNC16(smem, gptr) \
    asm volatile("cp.async.cg.shared.global [%0], [%1], 16;" ::"r"(smem), "l"(gptr) : "memory")
#define CP_COMMIT() asm volatile("cp.async.commit_group;" ::: "memory")
#define CP_WAIT3() asm volatile("cp.async.wait_group 3;" ::: "memory")

__device__ __forceinline__ void ldsm_x4(uint32_t* r, uint32_t addr) {
    asm volatile("ldmatrix.sync.aligned.m8n8.x4.shared.b16 {%0,%1,%2,%3}, [%4];"
                 : "=r"(r[0]), "=r"(r[1]), "=r"(r[2]), "=r"(r[3]) : "r"(addr));
}
__device__ __forceinline__ void mma_s8(int* d, const uint32_t* a, const uint32_t* b) {
    asm volatile(
        "mma.sync.aligned.m16n8k32.row.col.s32.s8.s8.s32 "
        "{%0,%1,%2,%3}, {%4,%5,%6,%7}, {%8,%9}, {%0,%1,%2,%3};"
        : "+r"(d[0]), "+r"(d[1]), "+r"(d[2]), "+r"(d[3])
        : "r"(a[0]), "r"(a[1]), "r"(a[2]), "r"(a[3]), "r"(b[0]), "r"(b[1]));
}

// ============================ kernel 1: absmax ==============================
__global__ void k_absmax(const float4* __restrict__ x, int n4) {
    float m = 0.0f;
    for (int i = blockIdx.x * blockDim.x + threadIdx.x; i < n4; i += gridDim.x * blockDim.x) {
        float4 v = x[i];
        m = fmaxf(m, fmaxf(fmaxf(fabsf(v.x), fabsf(v.y)), fmaxf(fabsf(v.z), fabsf(v.w))));
    }
    #pragma unroll
    for (int o = 16; o; o >>= 1) m = fmaxf(m, __shfl_xor_sync(0xFFFFFFFFu, m, o));
    __shared__ float sm[8];
    if ((threadIdx.x & 31) == 0) sm[threadIdx.x >> 5] = m;
    __syncthreads();
    if (threadIdx.x < 32) {
        float v = (threadIdx.x < 8) ? sm[threadIdx.x] : 0.0f;
        #pragma unroll
        for (int o = 4; o; o >>= 1) v = fmaxf(v, __shfl_xor_sync(0xFFFFFFFFu, v, o));
        if (threadIdx.x == 0) atomicMax(&g_absmax_bits, __float_as_int(v));  // v >= 0
    }
}

// ================== kernel 2: quantize x -> int8 [M][K] =====================
__device__ __forceinline__ int quant1(float v, float s) {
    float q = rintf(__fdiv_rn(v, s));  // IEEE div + round-half-even == jnp
    return (int)fminf(fmaxf(q, -128.0f), 127.0f);
}
__global__ void k_quant(const float4* __restrict__ x, int n4) {
    int i = blockIdx.x * blockDim.x + threadIdx.x;
    if (i >= n4) return;
    float s = __int_as_float(g_absmax_bits) * (1.0f / 128.0f);  // exact /128
    float4 v = x[i];
    uint32_t b0 = (uint32_t)(quant1(v.x, s) & 0xFF);
    uint32_t b1 = (uint32_t)(quant1(v.y, s) & 0xFF);
    uint32_t b2 = (uint32_t)(quant1(v.z, s) & 0xFF);
    uint32_t b3 = (uint32_t)(quant1(v.w, s) & 0xFF);
    reinterpret_cast<uint32_t*>(g_xq)[i] = b0 | (b1 << 8) | (b2 << 16) | (b3 << 24);
}

// ======== kernel 3: W [K][N] -> g_wt [N][K], register 4x4 PRMT transpose ====
__global__ void k_trans(const int8_t* __restrict__ W) {
    __shared__ uint32_t ts[64][17];
    int t = threadIdx.x;  // 256 threads
    int v0 = reinterpret_cast<const int*>(W)[t];
    int w_is32 = (__syncthreads_count(v0 >= -128 && v0 < 128) >= 250) ? 1 : 0;

    int n0 = blockIdx.x * 64, k0 = blockIdx.y * 64;
    int nb = t & 15, kb = t >> 4;

    uint32_t r[4];
    if (w_is32) {
        const int* W32 = reinterpret_cast<const int*>(W);
        #pragma unroll
        for (int i = 0; i < 4; ++i) {
            int4 v = *reinterpret_cast<const int4*>(
                &W32[(size_t)(k0 + kb * 4 + i) * NDIM + n0 + nb * 4]);
            r[i] = (v.x & 255) | ((v.y & 255) << 8) | ((v.z & 255) << 16)
                 | ((uint32_t)v.w << 24);
        }
    } else {
        #pragma unroll
        for (int i = 0; i < 4; ++i)
            r[i] = *reinterpret_cast<const uint32_t*>(
                &W[(size_t)(k0 + kb * 4 + i) * NDIM + n0 + nb * 4]);
    }
    uint32_t lo01 = __byte_perm(r[0], r[1], 0x5140);
    uint32_t hi01 = __byte_perm(r[0], r[1], 0x7362);
    uint32_t lo23 = __byte_perm(r[2], r[3], 0x5140);
    uint32_t hi23 = __byte_perm(r[2], r[3], 0x7362);
    ts[nb * 4 + 0][kb] = __byte_perm(lo01, lo23, 0x5410);
    ts[nb * 4 + 1][kb] = __byte_perm(lo01, lo23, 0x7632);
    ts[nb * 4 + 2][kb] = __byte_perm(hi01, hi23, 0x5410);
    ts[nb * 4 + 3][kb] = __byte_perm(hi01, hi23, 0x7632);
    __syncthreads();
    int n = t >> 2, ck = t & 3;
    uint32_t o0 = ts[n][ck * 4 + 0], o1 = ts[n][ck * 4 + 1];
    uint32_t o2 = ts[n][ck * 4 + 2], o3 = ts[n][ck * 4 + 3];
    *reinterpret_cast<uint4*>(&g_wt[(size_t)(n0 + n) * KDIM + k0 + ck * 16]) =
        make_uint4(o0, o1, o2, o3);
}

// ============================ kernel 4: GEMM ================================
// 128 threads; 4 warps in 2(M) x 2(N), warp tile 64x64; mma m16n8k32.
__global__ __launch_bounds__(NTHREADS, 2) void k_gemm(const float* __restrict__ bias,
                                                      float* __restrict__ out) {
    extern __shared__ char smem[];
    const uint32_t sb = smem_u32(smem);
    const int tid = threadIdx.x, lane = tid & 31;
    const int wid = tid >> 5;
    const int m0 = blockIdx.y * BM, n0 = blockIdx.x * BN;
    const int wm = (wid & 1) * 64;   // 2 warps along M
    const int wn = (wid >> 1) * 64;  // 2 warps along N

    const int8_t* ga = g_xq + (size_t)m0 * KDIM;
    const int8_t* gw = g_wt + (size_t)n0 * KDIM;

    // one stage = 512 A-chunks + 512 B-chunks of 16B; 128 threads -> 4+4 each
    auto load_stage = [&](int s, int kt) {
        uint32_t abase = sb + s * STAGE_BYTES;
        uint32_t bbase = abase + A_TILE;
        int k0 = kt * BK;
        #pragma unroll
        for (int i = 0; i < 4; ++i) {
            int idx = tid + i * NTHREADS;  // 0..511
            uint32_t r = (uint32_t)idx >> 2, c = (uint32_t)idx & 3;
            CP_ASYNC16(abase + tile_off(r, c), ga + (size_t)r * KDIM + k0 + c * 16);
            CP_ASYNC16(bbase + tile_off(r, c), gw + (size_t)r * KDIM + k0 + c * 16);
        }
    };

    // fragment load for one k32 step (column pair j)
    auto load_frags = [&](uint32_t abase, uint32_t bbase, int j,
                          uint32_t (&af)[4][4], uint32_t (&bf)[4][4]) {
        #pragma unroll
        for (int f = 0; f < 4; ++f) {
            uint32_t r = (uint32_t)(wm + f * 16 + (lane & 15));
            uint32_t c = (uint32_t)(2 * j + (lane >> 4));
            ldsm_x4(af[f], abase + tile_off(r, c));
        }
        #pragma unroll
        for (int p = 0; p < 4; ++p) {
            uint32_t r = (uint32_t)(wn + p * 16 + (lane & 7) + ((lane >> 4) << 3));
            uint32_t c = (uint32_t)(2 * j + ((lane >> 3) & 1));
            ldsm_x4(bf[p], bbase + tile_off(r, c));
        }
    };

    int acc[4][8][4];
    #pragma unroll
    for (int a = 0; a < 4; ++a)
        #pragma unroll
        for (int b = 0; b < 8; ++b)
            #pragma unroll
            for (int c = 0; c < 4; ++c) acc[a][b][c] = 0;

    auto do_mma = [&](uint32_t (&af)[4][4], uint32_t (&bf)[4][4]) {
        #pragma unroll
        for (int f = 0; f < 4; ++f)
            #pragma unroll
            for (int nf = 0; nf < 8; ++nf)
                mma_s8(acc[f][nf], af[f], &bf[nf >> 1][(nf & 1) * 2]);
    };

    #pragma unroll
    for (int s = 0; s < STAGES - 1; ++s) {
        load_stage(s, s);
        CP_COMMIT();
    }

    int stage = 0;  // decoupled from kt (STAGES=5 not a power of two)
    #pragma unroll 1
    for (int kt = 0; kt < NIT; ++kt) {
        CP_WAIT3();
        __syncthreads();

        uint32_t abase = sb + stage * STAGE_BYTES;
        uint32_t bbase = abase + A_TILE;
        uint32_t a0[4][4], b0f[4][4], a1[4][4], b1f[4][4];

        // j=0 ldsm FIRST (latency overlaps the cp.async issue burst below)
        load_frags(abase, bbase, 0, a0, b0f);
        {
            int pf = kt + STAGES - 1;
            if (pf < NIT) {
                int ps = stage + STAGES - 1;
                if (ps >= STAGES) ps -= STAGES;
                load_stage(ps, pf);
            }
        }
        CP_COMMIT();  // always commit -> uniform group counting (tail-safe)

        // j=1 ldsm issued before j=0 mma: its latency hides under 32 mma ops
        load_frags(abase, bbase, 1, a1, b1f);
        do_mma(a0, b0f);
        do_mma(a1, b1f);

        if (++stage == STAGES) stage = 0;
    }

    // ---------------- epilogue: y = acc * sc + bias ----------------
    const float sc = (__int_as_float(g_absmax_bits) * (1.0f / 128.0f)) * 0.0123f;
    const int g = lane >> 2, t4 = lane & 3;
    #pragma unroll
    for (int f = 0; f < 4; ++f) {
        #pragma unroll
        for (int nf = 0; nf < 8; ++nf) {
            int col = n0 + wn + nf * 8 + 2 * t4;
            float b0 = bias[col], b1 = bias[col + 1];
            #pragma unroll
            for (int h = 0; h < 2; ++h) {  // c0,c1 -> row g; c2,c3 -> row g+8
                int row = m0 + wm + f * 16 + g + h * 8;
                float2 v;
                v.x = fmaf((float)acc[f][nf][2 * h + 0], sc, b0);
                v.y = fmaf((float)acc[f][nf][2 * h + 1], sc, b1);
                *reinterpret_cast<float2*>(&out[(size_t)row * NDIM + col]) = v;
            }
        }
    }
}

// ============================ host launcher =================================
extern "C" void kernel_launch(void* const* d_in, const int* in_sizes, int n_in,
                              void* d_out, int out_size) {
    const float* x = nullptr;
    const int8_t* W = nullptr;
    const float* bias = nullptr;
    for (int i = 0; i < n_in; ++i) {
        long long sz = in_sizes[i];
        if (sz == (long long)MDIM * KDIM) x = (const float*)d_in[i];
        else if (sz == (long long)KDIM * NDIM) W = (const int8_t*)d_in[i];
        else if (sz == (long long)NDIM) bias = (const float*)d_in[i];
    }
    float* out = (float*)d_out;

    const int n4 = MDIM * KDIM / 4;
    k_absmax<<<1024, 256>>>((const float4*)x, n4);
    k_quant<<<n4 / 256, 256>>>((const float4*)x, n4);
    k_trans<<<dim3(NDIM / 64, KDIM / 64), 256>>>(W);

    cudaFuncSetAttribute(k_gemm, cudaFuncAttributeMaxDynamicSharedMemorySize, SMEM_TOTAL);
    k_gemm<<<dim3(NDIM / BN, MDIM / BM), NTHREADS, SMEM_TOTAL>>>(bias, out);
}

// round 12
// speedup vs baseline: 1.1433x; 1.0008x over previous
#include <cuda_runtime.h>
#include <cstdint>
#include <cstddef>

// ============================================================================
// y = (x_q @ W) * (x_scale * 0.0123) + bias     [M,K]x[K,N] = 2048x4096x11008
// sm_100 base target. cp.async + ldmatrix + mma.sync.m16n8k32.s8.s8.s32.
// R12 == R11 resubmit (R11 never executed: container infra flake — same
// signature as R0's no-op stub, R6, R8; identical resubmits passed R7/R9).
// R11 = R7 compute ordering (measured best: GEMM 231.5us / tensor 74.3%)
//     + decoupled barrier schedule: 7 stages, per-kt commits, wait_group 4,
//       prefetch distance S-2 (write slot last read 2 iters ago) ->
//       __syncthreads() only every SECOND iteration (32 barriers, was 64)
//       while pipeline depth INCREASES 3->4 kt (R8 failed by coupling these).
// ============================================================================

#define MDIM 2048
#define KDIM 4096
#define NDIM 11008

#define BM 128
#define BN 128
#define BK 64
#define STAGES 7
#define NIT (KDIM / BK) /* 64 */
#define NTHREADS 128
#define PF_DIST (STAGES - 2) /* 5: prefetch kt+5; written slot read at t-2 */

#define A_TILE (BM * BK)          /* 8192 B */
#define B_TILE (BN * BK)          /* 8192 B */
#define STAGE_BYTES (A_TILE + B_TILE)
#define SMEM_TOTAL (STAGES * STAGE_BYTES) /* 114688 = 112KB; 2 CTAs = 224KB */

// ---------------- device scratch (__device__ globals: allowed) --------------
__device__ __align__(128) int8_t g_xq[(size_t)MDIM * KDIM];  // [M][K]
__device__ __align__(128) int8_t g_wt[(size_t)NDIM * KDIM];  // [N][K] (= W^T)
__device__ int g_absmax_bits;  // static zero; idempotent across graph replays

// smem tile layout: 16B chunk c of row r at r*64 + (c ^ ((r>>1)&3))*16.
__device__ __forceinline__ uint32_t tile_off(uint32_t r, uint32_t c) {
    return r * 64u + ((c ^ ((r >> 1) & 3u)) << 4);
}

__device__ __forceinline__ uint32_t smem_u32(const void* p) {
    uint32_t a;
    asm("{ .reg .u64 t; cvta.to.shared.u64 t, %1; cvt.u32.u64 %0, t; }" : "=r"(a) : "l"(p));
    return a;
}
#define CP_ASYNC16(smem, gptr) \
    asm volatile("cp.async.cg.shared.global [%0], [%1], 16;" ::"r"(smem), "l"(gptr) : "memory")
#define CP_COMMIT() asm volatile("cp.async.commit_group;" ::: "memory")
#define CP_WAIT4() asm volatile("cp.async.wait_group 4;" ::: "memory")

__device__ __forceinline__ void ldsm_x4(uint32_t* r, uint32_t addr) {
    asm volatile("ldmatrix.sync.aligned.m8n8.x4.shared.b16 {%0,%1,%2,%3}, [%4];"
                 : "=r"(r[0]), "=r"(r[1]), "=r"(r[2]), "=r"(r[3]) : "r"(addr));
}
__device__ __forceinline__ void mma_s8(int* d, const uint32_t* a, const uint32_t* b) {
    asm volatile(
        "mma.sync.aligned.m16n8k32.row.col.s32.s8.s8.s32 "
        "{%0,%1,%2,%3}, {%4,%5,%6,%7}, {%8,%9}, {%0,%1,%2,%3};"
        : "+r"(d[0]), "+r"(d[1]), "+r"(d[2]), "+r"(d[3])
        : "r"(a[0]), "r"(a[1]), "r"(a[2]), "r"(a[3]), "r"(b[0]), "r"(b[1]));
}

// ============================ kernel 1: absmax ==============================
__global__ void k_absmax(const float4* __restrict__ x, int n4) {
    float m = 0.0f;
    for (int i = blockIdx.x * blockDim.x + threadIdx.x; i < n4; i += gridDim.x * blockDim.x) {
        float4 v = x[i];
        m = fmaxf(m, fmaxf(fmaxf(fabsf(v.x), fabsf(v.y)), fmaxf(fabsf(v.z), fabsf(v.w))));
    }
    #pragma unroll
    for (int o = 16; o; o >>= 1) m = fmaxf(m, __shfl_xor_sync(0xFFFFFFFFu, m, o));
    __shared__ float sm[8];
    if ((threadIdx.x & 31) == 0) sm[threadIdx.x >> 5] = m;
    __syncthreads();
    if (threadIdx.x < 32) {
        float v = (threadIdx.x < 8) ? sm[threadIdx.x] : 0.0f;
        #pragma unroll
        for (int o = 4; o; o >>= 1) v = fmaxf(v, __shfl_xor_sync(0xFFFFFFFFu, v, o));
        if (threadIdx.x == 0) atomicMax(&g_absmax_bits, __float_as_int(v));  // v >= 0
    }
}

// ================== kernel 2: quantize x -> int8 [M][K] =====================
__device__ __forceinline__ int quant1(float v, float s) {
    float q = rintf(__fdiv_rn(v, s));  // IEEE div + round-half-even == jnp
    return (int)fminf(fmaxf(q, -128.0f), 127.0f);
}
__global__ void k_quant(const float4* __restrict__ x, int n4) {
    int i = blockIdx.x * blockDim.x + threadIdx.x;
    if (i >= n4) return;
    float s = __int_as_float(g_absmax_bits) * (1.0f / 128.0f);  // exact /128
    float4 v = x[i];
    uint32_t b0 = (uint32_t)(quant1(v.x, s) & 0xFF);
    uint32_t b1 = (uint32_t)(quant1(v.y, s) & 0xFF);
    uint32_t b2 = (uint32_t)(quant1(v.z, s) & 0xFF);
    uint32_t b3 = (uint32_t)(quant1(v.w, s) & 0xFF);
    reinterpret_cast<uint32_t*>(g_xq)[i] = b0 | (b1 << 8) | (b2 << 16) | (b3 << 24);
}

// ======== kernel 3: W [K][N] -> g_wt [N][K], register 4x4 PRMT transpose ====
__global__ void k_trans(const int8_t* __restrict__ W) {
    __shared__ uint32_t ts[64][17];
    int t = threadIdx.x;  // 256 threads
    int v0 = reinterpret_cast<const int*>(W)[t];
    int w_is32 = (__syncthreads_count(v0 >= -128 && v0 < 128) >= 250) ? 1 : 0;

    int n0 = blockIdx.x * 64, k0 = blockIdx.y * 64;
    int nb = t & 15, kb = t >> 4;

    uint32_t r[4];
    if (w_is32) {
        const int* W32 = reinterpret_cast<const int*>(W);
        #pragma unroll
        for (int i = 0; i < 4; ++i) {
            int4 v = *reinterpret_cast<const int4*>(
                &W32[(size_t)(k0 + kb * 4 + i) * NDIM + n0 + nb * 4]);
            r[i] = (v.x & 255) | ((v.y & 255) << 8) | ((v.z & 255) << 16)
                 | ((uint32_t)v.w << 24);
        }
    } else {
        #pragma unroll
        for (int i = 0; i < 4; ++i)
            r[i] = *reinterpret_cast<const uint32_t*>(
                &W[(size_t)(k0 + kb * 4 + i) * NDIM + n0 + nb * 4]);
    }
    uint32_t lo01 = __byte_perm(r[0], r[1], 0x5140);
    uint32_t hi01 = __byte_perm(r[0], r[1], 0x7362);
    uint32_t lo23 = __byte_perm(r[2], r[3], 0x5140);
    uint32_t hi23 = __byte_perm(r[2], r[3], 0x7362);
    ts[nb * 4 + 0][kb] = __byte_perm(lo01, lo23, 0x5410);
    ts[nb * 4 + 1][kb] = __byte_perm(lo01, lo23, 0x7632);
    ts[nb * 4 + 2][kb] = __byte_perm(hi01, hi23, 0x5410);
    ts[nb * 4 + 3][kb] = __byte_perm(hi01, hi23, 0x7632);
    __syncthreads();
    int n = t >> 2, ck = t & 3;
    uint32_t o0 = ts[n][ck * 4 + 0], o1 = ts[n][ck * 4 + 1];
    uint32_t o2 = ts[n][ck * 4 + 2], o3 = ts[n][ck * 4 + 3];
    *reinterpret_cast<uint4*>(&g_wt[(size_t)(n0 + n) * KDIM + k0 + ck * 16]) =
        make_uint4(o0, o1, o2, o3);
}

// ============================ kernel 4: GEMM ================================
// 128 threads; 4 warps in 2(M) x 2(N), warp tile 64x64; mma m16n8k32.
__global__ __launch_bounds__(NTHREADS, 2) void k_gemm(const float* __restrict__ bias,
                                                      float* __restrict__ out) {
    extern __shared__ char smem[];
    const uint32_t sb = smem_u32(smem);
    const int tid = threadIdx.x, lane = tid & 31;
    const int wid = tid >> 5;
    const int m0 = blockIdx.y * BM, n0 = blockIdx.x * BN;
    const int wm = (wid & 1) * 64;   // 2 warps along M
    const int wn = (wid >> 1) * 64;  // 2 warps along N

    const int8_t* ga = g_xq + (size_t)m0 * KDIM;
    const int8_t* gw = g_wt + (size_t)n0 * KDIM;

    // one stage = 512 A-chunks + 512 B-chunks of 16B; 128 threads -> 4+4 each
    auto load_stage = [&](int s, int kt) {
        uint32_t abase = sb + s * STAGE_BYTES;
        uint32_t bbase = abase + A_TILE;
        int k0 = kt * BK;
        #pragma unroll
        for (int i = 0; i < 4; ++i) {
            int idx = tid + i * NTHREADS;  // 0..511
            uint32_t r = (uint32_t)idx >> 2, c = (uint32_t)idx & 3;
            CP_ASYNC16(abase + tile_off(r, c), ga + (size_t)r * KDIM + k0 + c * 16);
            CP_ASYNC16(bbase + tile_off(r, c), gw + (size_t)r * KDIM + k0 + c * 16);
        }
    };

    int acc[4][8][4];
    #pragma unroll
    for (int a = 0; a < 4; ++a)
        #pragma unroll
        for (int b = 0; b < 8; ++b)
            #pragma unroll
            for (int c = 0; c < 4; ++c) acc[a][b][c] = 0;

    // prologue: PF_DIST groups, one stage each (kt 0..4 -> slots 0..4)
    #pragma unroll
    for (int s = 0; s < PF_DIST; ++s) {
        load_stage(s, s);
        CP_COMMIT();
    }

    int stage = 0;  // = kt mod 7
    #pragma unroll 1
    for (int kt = 0; kt < NIT; ++kt) {
        CP_WAIT4();
        if ((kt & 1) == 0) __syncthreads();  // WAR distance is 2 iters -> every
                                             // other barrier suffices
        {
            int pf = kt + PF_DIST;
            if (pf < NIT) {
                int ps = stage + PF_DIST;
                if (ps >= STAGES) ps -= STAGES;
                load_stage(ps, pf);  // slot last READ at iteration kt-2
            }
        }
        CP_COMMIT();  // always commit -> uniform group counting (tail-safe)

        uint32_t abase = sb + stage * STAGE_BYTES;
        uint32_t bbase = abase + A_TILE;
        #pragma unroll
        for (int j = 0; j < 2; ++j) {  // two k32 steps per BK (R7 ordering)
            uint32_t af[4][4], bf[4][4];
            #pragma unroll
            for (int f = 0; f < 4; ++f) {
                uint32_t r = (uint32_t)(wm + f * 16 + (lane & 15));
                uint32_t c = (uint32_t)(2 * j + (lane >> 4));
                ldsm_x4(af[f], abase + tile_off(r, c));
            }
            #pragma unroll
            for (int p = 0; p < 4; ++p) {
                uint32_t r = (uint32_t)(wn + p * 16 + (lane & 7) + ((lane >> 4) << 3));
                uint32_t c = (uint32_t)(2 * j + ((lane >> 3) & 1));
                ldsm_x4(bf[p], bbase + tile_off(r, c));
            }
            #pragma unroll
            for (int f = 0; f < 4; ++f)
                #pragma unroll
                for (int nf = 0; nf < 8; ++nf)
                    mma_s8(acc[f][nf], af[f], &bf[nf >> 1][(nf & 1) * 2]);
        }
        if (++stage == STAGES) stage = 0;
    }

    // ---------------- epilogue: y = acc * sc + bias ----------------
    const float sc = (__int_as_float(g_absmax_bits) * (1.0f / 128.0f)) * 0.0123f;
    const int g = lane >> 2, t4 = lane & 3;
    #pragma unroll
    for (int f = 0; f < 4; ++f) {
        #pragma unroll
        for (int nf = 0; nf < 8; ++nf) {
            int col = n0 + wn + nf * 8 + 2 * t4;
            float b0 = bias[col], b1 = bias[col + 1];
            #pragma unroll
            for (int h = 0; h < 2; ++h) {  // c0,c1 -> row g; c2,c3 -> row g+8
                int row = m0 + wm + f * 16 + g + h * 8;
                float2 v;
                v.x = fmaf((float)acc[f][nf][2 * h + 0], sc, b0);
                v.y = fmaf((float)acc[f][nf][2 * h + 1], sc, b1);
                *reinterpret_cast<float2*>(&out[(size_t)row * NDIM + col]) = v;
            }
        }
    }
}

// ============================ host launcher =================================
extern "C" void kernel_launch(void* const* d_in, const int* in_sizes, int n_in,
                              void* d_out, int out_size) {
    const float* x = nullptr;
    const int8_t* W = nullptr;
    const float* bias = nullptr;
    for (int i = 0; i < n_in; ++i) {
        long long sz = in_sizes[i];
        if (sz == (long long)MDIM * KDIM) x = (const float*)d_in[i];
        else if (sz == (long long)KDIM * NDIM) W = (const int8_t*)d_in[i];
        else if (sz == (long long)NDIM) bias = (const float*)d_in[i];
    }
    float* out = (float*)d_out;

    const int n4 = MDIM * KDIM / 4;
    k_absmax<<<1024, 256>>>((const float4*)x, n4);
    k_quant<<<n4 / 256, 256>>>((const float4*)x, n4);
    k_trans<<<dim3(NDIM / 64, KDIM / 64), 256>>>(W);

    cudaFuncSetAttribute(k_gemm, cudaFuncAttributeMaxDynamicSharedMemorySize, SMEM_TOTAL);
    k_gemm<<<dim3(NDIM / BN, MDIM / BM), NTHREADS, SMEM_TOTAL>>>(bias, out);
}